// round 4
// baseline (speedup 1.0000x reference)
#include <cuda_runtime.h>
#include <cstddef>
#include <cstdint>

#define B_   2
#define N_   768
#define BN_  1536
#define D_   512
#define E_   64
#define LN_EPS 1e-5f
#define PADR 68            // kC smem row pitch (floats)
#define XP   130           // kB x-tile pitch (floats)

typedef unsigned long long ull;

// ---------------- scratch ----------------
__device__ float g_WR[D_ * E_];     // fused W_edges@W_rows, [d][f]
__device__ float g_WC[D_ * E_];     // fused W_edges@W_cols, [d][f]
__device__ float g_Rc[BN_ * E_];    // centered R'
__device__ float g_Cc[BN_ * E_];    // centered C'
__device__ float g_varR[BN_];
__device__ float g_varC[BN_];

// -------- f32x2 helpers --------
__device__ __forceinline__ void ffma2(ull& d, ull a, ull b) {
    asm("fma.rn.f32x2 %0, %1, %2, %0;" : "+l"(d) : "l"(a), "l"(b));
}
__device__ __forceinline__ ull pack2(float x) {
    ull r; unsigned u = __float_as_uint(x);
    asm("mov.b64 %0, {%1, %1};" : "=l"(r) : "r"(u));
    return r;
}

// ---------------- kernel A v3: K-split fused-weight build --------------------
// task = (fh[5b], d2[8b], k8[3b]); thread computes 8-e partial of 2 f-outputs
// for a d-pair; butterfly-reduce over the 8 k8 lanes; lane k8==0 stores.
// 256 blocks x 256 thr = 65536 tasks. No long serial load chains anywhere.
__global__ void __launch_bounds__(256) kA(const float* __restrict__ We,
                                          const float* __restrict__ Wr,
                                          const float* __restrict__ Wc) {
    int task = blockIdx.x * 256 + threadIdx.x;
    int k8 = task & 7;
    int d2 = (task >> 3) & 255;
    int fh = task >> 11;           // 0..31
    int f0 = fh, f1 = fh + 32;

    float2 ar0 = {0.f, 0.f}, ar1 = {0.f, 0.f};
    float2 ac0 = {0.f, 0.f}, ac1 = {0.f, 0.f};
    const float* we0p = We + f0 * E_ + k8 * 8;
    const float* we1p = We + f1 * E_ + k8 * 8;
#pragma unroll
    for (int e = 0; e < 8; e++) {
        int ge = k8 * 8 + e;
        float2 wr = *(const float2*)(Wr + (size_t)ge * D_ + d2 * 2);
        float2 wc = *(const float2*)(Wc + (size_t)ge * D_ + d2 * 2);
        float w0 = we0p[e], w1 = we1p[e];
        ar0.x = fmaf(w0, wr.x, ar0.x); ar0.y = fmaf(w0, wr.y, ar0.y);
        ar1.x = fmaf(w1, wr.x, ar1.x); ar1.y = fmaf(w1, wr.y, ar1.y);
        ac0.x = fmaf(w0, wc.x, ac0.x); ac0.y = fmaf(w0, wc.y, ac0.y);
        ac1.x = fmaf(w1, wc.x, ac1.x); ac1.y = fmaf(w1, wc.y, ac1.y);
    }
#pragma unroll
    for (int o = 4; o; o >>= 1) {
        ar0.x += __shfl_xor_sync(0xffffffffu, ar0.x, o);
        ar0.y += __shfl_xor_sync(0xffffffffu, ar0.y, o);
        ar1.x += __shfl_xor_sync(0xffffffffu, ar1.x, o);
        ar1.y += __shfl_xor_sync(0xffffffffu, ar1.y, o);
        ac0.x += __shfl_xor_sync(0xffffffffu, ac0.x, o);
        ac0.y += __shfl_xor_sync(0xffffffffu, ac0.y, o);
        ac1.x += __shfl_xor_sync(0xffffffffu, ac1.x, o);
        ac1.y += __shfl_xor_sync(0xffffffffu, ac1.y, o);
    }
    if (k8 == 0) {
        int d0 = d2 * 2;
        g_WR[(d0 + 0) * E_ + f0] = ar0.x;
        g_WR[(d0 + 1) * E_ + f0] = ar0.y;
        g_WR[(d0 + 0) * E_ + f1] = ar1.x;
        g_WR[(d0 + 1) * E_ + f1] = ar1.y;
        g_WC[(d0 + 0) * E_ + f0] = ac0.x;
        g_WC[(d0 + 1) * E_ + f0] = ac0.y;
        g_WC[(d0 + 0) * E_ + f1] = ac1.x;
        g_WC[(d0 + 1) * E_ + f1] = ac1.y;
    }
}

// ---------------- kernel B: row GEMM + center + variance, fully fused --------
// (unchanged from R3 — working, ~few us)
extern __shared__ float sm_b[];
__global__ void __launch_bounds__(256) kB(const float* __restrict__ x) {
    float* xs  = sm_b;            // 2080 floats
    float* wrs = sm_b + 2080;     // 8192 floats
    float* wcs = wrs + 8192;      // 8192 floats
    float* P   = sm_b + 2080;     // alias: 16384 floats

    int tid  = threadIdx.x;
    int f2   = tid & 31;
    int w    = tid >> 5;
    int row0 = blockIdx.x * 16;

    ull aR[16], aC[16];
#pragma unroll
    for (int r = 0; r < 16; r++) { aR[r] = 0ULL; aC[r] = 0ULL; }

    for (int c = 0; c < 4; c++) {
        int d0 = c * 128;
        for (int idx = tid; idx < 2048; idx += 256) {
            ((float4*)wrs)[idx] = ((const float4*)(g_WR + d0 * E_))[idx];
            ((float4*)wcs)[idx] = ((const float4*)(g_WC + d0 * E_))[idx];
        }
        for (int idx = tid; idx < 1024; idx += 256) {
            int r = idx >> 6, dd2 = idx & 63;
            *(float2*)(xs + r * XP + dd2 * 2) =
                *(const float2*)(x + (size_t)(row0 + r) * D_ + d0 + dd2 * 2);
        }
        __syncthreads();

        int wbase = w * 16;
#pragma unroll
        for (int p = 0; p < 8; p++) {
            int dd = wbase + p * 2;
            ull wr0 = *(const ull*)(wrs + dd * E_ + 2 * f2);
            ull wr1 = *(const ull*)(wrs + (dd + 1) * E_ + 2 * f2);
            ull wc0 = *(const ull*)(wcs + dd * E_ + 2 * f2);
            ull wc1 = *(const ull*)(wcs + (dd + 1) * E_ + 2 * f2);
#pragma unroll
            for (int r = 0; r < 16; r++) {
                float2 xv = *(const float2*)(xs + r * XP + dd);
                ull x0 = pack2(xv.x);
                ull x1 = pack2(xv.y);
                ffma2(aR[r], x0, wr0);
                ffma2(aR[r], x1, wr1);
                ffma2(aC[r], x0, wc0);
                ffma2(aC[r], x1, wc1);
            }
        }
        __syncthreads();
    }

#pragma unroll
    for (int r = 0; r < 16; r++) {
        *(ull*)(P + ((w * 2 + 0) * 16 + r) * E_ + 2 * f2) = aR[r];
        *(ull*)(P + ((w * 2 + 1) * 16 + r) * E_ + 2 * f2) = aC[r];
    }
    __syncthreads();

    int row = tid >> 4;
    int fq  = tid & 15;
    float4 R4 = make_float4(0.f, 0.f, 0.f, 0.f);
    float4 C4 = make_float4(0.f, 0.f, 0.f, 0.f);
#pragma unroll
    for (int ww = 0; ww < 8; ww++) {
        float4 pr = *(const float4*)(P + ((ww * 2 + 0) * 16 + row) * E_ + fq * 4);
        float4 pc = *(const float4*)(P + ((ww * 2 + 1) * 16 + row) * E_ + fq * 4);
        R4.x += pr.x; R4.y += pr.y; R4.z += pr.z; R4.w += pr.w;
        C4.x += pc.x; C4.y += pc.y; C4.z += pc.z; C4.w += pc.w;
    }
    float sR  = R4.x + R4.y + R4.z + R4.w;
    float sRR = R4.x * R4.x + R4.y * R4.y + R4.z * R4.z + R4.w * R4.w;
    float sC  = C4.x + C4.y + C4.z + C4.w;
    float sCC = C4.x * C4.x + C4.y * C4.y + C4.z * C4.z + C4.w * C4.w;
#pragma unroll
    for (int o = 1; o < 16; o <<= 1) {
        sR  += __shfl_xor_sync(0xffffffffu, sR,  o);
        sRR += __shfl_xor_sync(0xffffffffu, sRR, o);
        sC  += __shfl_xor_sync(0xffffffffu, sC,  o);
        sCC += __shfl_xor_sync(0xffffffffu, sCC, o);
    }
    float mR = sR * (1.f / 64.f);
    float mC = sC * (1.f / 64.f);
    int grow = row0 + row;
    float4 oR = make_float4(R4.x - mR, R4.y - mR, R4.z - mR, R4.w - mR);
    float4 oC = make_float4(C4.x - mC, C4.y - mC, C4.z - mC, C4.w - mC);
    *(float4*)(g_Rc + grow * E_ + fq * 4) = oR;
    *(float4*)(g_Cc + grow * E_ + fq * 4) = oC;
    if (fq == 0) {
        g_varR[grow] = sRR * (1.f / 64.f) - mR * mR;
        g_varC[grow] = sCC * (1.f / 64.f) - mC * mC;
    }
}

// ---------------- kernel C: 16i x 32j tile, dots -> inv-std, streaming -------
__global__ void __launch_bounds__(256) kC(const float* __restrict__ gamma,
                                          const float* __restrict__ beta,
                                          float* __restrict__ out) {
    __shared__ float rs[16 * PADR];    // raw R'
    __shared__ float cs[32 * PADR];    // raw C' (dots)
    __shared__ float csg[32 * PADR];   // C' * gamma (stores)
    __shared__ float vR[16];
    __shared__ float vC[32];
    __shared__ float inv[512];

    int i0 = blockIdx.x * 16;
    int j0 = blockIdx.y * 32;
    int b  = blockIdx.z;
    int tid = threadIdx.x;
    int rowR = b * N_ + i0;
    int rowC = b * N_ + j0;

    for (int idx = tid; idx < 32 * E_; idx += 256) {
        int r = idx >> 6, f = idx & 63;
        float cv = g_Cc[(rowC + r) * E_ + f];
        cs[r * PADR + f]  = cv;
        csg[r * PADR + f] = cv * __ldg(gamma + f);
    }
    for (int idx = tid; idx < 16 * E_; idx += 256) {
        int r = idx >> 6, f = idx & 63;
        rs[r * PADR + f] = g_Rc[(rowR + r) * E_ + f];
    }
    if (tid < 16)      vR[tid]      = g_varR[rowR + tid];
    else if (tid < 48) vC[tid - 16] = g_varC[rowC + tid - 16];
    __syncthreads();

    // ---- Phase A: 512 dots, 2 per thread ----
#pragma unroll
    for (int t = tid; t < 512; t += 256) {
        int ii = t >> 5, jj = t & 31;
        const float4* r4 = (const float4*)(rs + ii * PADR);
        const float4* c4 = (const float4*)(cs + jj * PADR);
        float d = 0.f;
#pragma unroll
        for (int k = 0; k < 16; k++) {
            float4 a = r4[k], c = c4[k];
            d = fmaf(a.x, c.x, d);
            d = fmaf(a.y, c.y, d);
            d = fmaf(a.z, c.z, d);
            d = fmaf(a.w, c.w, d);
        }
        float var = vR[ii] + vC[jj] + d * (2.f / 64.f);
        inv[t] = rsqrtf(var + LN_EPS);
    }
    __syncthreads();

    // ---- Phase B: streaming stores ----
    int f4 = tid & 15;
    int g  = tid >> 4;
    float4 gm = __ldg((const float4*)gamma + f4);
    float4 bt = __ldg((const float4*)beta + f4);
    float4 r  = ((const float4*)(rs + g * PADR))[f4];
    float4 u;
    u.x = r.x * gm.x; u.y = r.y * gm.y; u.z = r.z * gm.z; u.w = r.w * gm.w;

    const float* invg = inv + g * 32;
    float4* op = (float4*)out + ((size_t)(b * N_ + i0 + g) * N_ + j0) * 16 + f4;

#pragma unroll
    for (int jj = 0; jj < 32; jj++) {
        float4 v = ((const float4*)(csg + jj * PADR))[f4];
        float iv = invg[jj];
        float4 o;
        o.x = fmaf(u.x + v.x, iv, bt.x);
        o.y = fmaf(u.y + v.y, iv, bt.y);
        o.z = fmaf(u.z + v.z, iv, bt.z);
        o.w = fmaf(u.w + v.w, iv, bt.w);
        __stcs(op + (size_t)jj * 16, o);
    }
}

// ---------------- launch -------------------------------------------------------
extern "C" void kernel_launch(void* const* d_in, const int* in_sizes, int n_in,
                              void* d_out, int out_size) {
    const float* x     = (const float*)d_in[0];  // [2,768,512]
    const float* Wr    = (const float*)d_in[1];  // [64,512]
    const float* Wc    = (const float*)d_in[2];  // [64,512]
    const float* We    = (const float*)d_in[3];  // [64,64]
    const float* gamma = (const float*)d_in[4];  // [64]
    const float* beta  = (const float*)d_in[5];  // [64]
    float* out = (float*)d_out;                  // [2,768,768,64] fp32

    static int smem_set = 0;
    if (!smem_set) {
        cudaFuncSetAttribute(kB, cudaFuncAttributeMaxDynamicSharedMemorySize, 73856);
        smem_set = 1;
    }

    kA<<<256, 256>>>(We, Wr, Wc);
    kB<<<96, 256, 73856>>>(x);
    kC<<<dim3(N_ / 16, N_ / 32, B_), 256>>>(gamma, beta, out);
}

// round 5
// speedup vs baseline: 1.0791x; 1.0791x over previous
#include <cuda_runtime.h>
#include <cstddef>
#include <cstdint>

#define B_   2
#define N_   768
#define BN_  1536
#define D_   512
#define E_   64
#define LN_EPS 1e-5f
#define PADR 68            // kC smem row pitch (floats)
#define XP   130           // kB x-tile pitch (floats)
#define WPITCH 66          // kB weight-tile pitch (floats): dd-major, [dd][e]

typedef unsigned long long ull;

// ---------------- scratch ----------------
__device__ float g_Rc[BN_ * E_];    // centered R'
__device__ float g_Cc[BN_ * E_];    // centered C'
__device__ float g_varR[BN_];
__device__ float g_varC[BN_];

// -------- f32x2 helpers --------
__device__ __forceinline__ void ffma2(ull& d, ull a, ull b) {
    asm("fma.rn.f32x2 %0, %1, %2, %0;" : "+l"(d) : "l"(a), "l"(b));
}
__device__ __forceinline__ ull pack2(float x) {
    ull r; unsigned u = __float_as_uint(x);
    asm("mov.b64 %0, {%1, %1};" : "=l"(r) : "r"(u));
    return r;
}

// ---------------- kernel B: x@Wrt, x@Wct, then @Wet, center, variance --------
// grid 96, block 256. Per block: 16 rows.
// smem: xs[16*XP]=2080 | wrs[128*WPITCH]=8448 | wcs=8448 | wes[64*65]=4160
// P (warp partials, 16384 floats) aliases wrs+wcs after the last chunk;
// rS/cS (raw rows/cols, 1024 each) alias xs after the last chunk.
extern __shared__ float sm_b[];
__global__ void __launch_bounds__(256) kB(const float* __restrict__ x,
                                          const float* __restrict__ Wr,
                                          const float* __restrict__ Wc,
                                          const float* __restrict__ We) {
    float* xs  = sm_b;                 // 2080
    float* wrs = sm_b + 2080;          // 8448
    float* wcs = wrs + 8448;           // 8448
    float* wes = wcs + 8448;           // 4160
    float* P   = sm_b + 2080;          // alias (16384 <= 16896)
    float* rS  = sm_b;                 // alias (1024)
    float* cS  = sm_b + 1024;          // alias (1024)
    __shared__ float red[8][4][4];     // [warp][row-in-group][quantity]

    int tid  = threadIdx.x;
    int f2   = tid & 31;
    int w    = tid >> 5;
    int row0 = blockIdx.x * 16;

    // load We transposed: wes[e*65 + f] = We[f*64 + e]  (conflict-free both ways)
    for (int idx = tid; idx < 4096; idx += 256) {
        int f = idx >> 6, e = idx & 63;
        wes[e * 65 + f] = We[f * E_ + e];
    }

    ull aR[16], aC[16];
#pragma unroll
    for (int r = 0; r < 16; r++) { aR[r] = 0ULL; aC[r] = 0ULL; }

    for (int c = 0; c < 4; c++) {
        int d0 = c * 128;
        // raw weights transposed into [dd][e] (pitch 66): read coalesced along d
        for (int idx = tid; idx < 8192; idx += 256) {
            int dd = idx & 127, e = idx >> 7;
            wrs[dd * WPITCH + e] = Wr[(size_t)e * D_ + d0 + dd];
            wcs[dd * WPITCH + e] = Wc[(size_t)e * D_ + d0 + dd];
        }
        // x tile: 16 rows x 128 dd
        for (int idx = tid; idx < 1024; idx += 256) {
            int r = idx >> 6, dd2 = idx & 63;
            *(float2*)(xs + r * XP + dd2 * 2) =
                *(const float2*)(x + (size_t)(row0 + r) * D_ + d0 + dd2 * 2);
        }
        __syncthreads();

        int wbase = w * 16;
#pragma unroll
        for (int p = 0; p < 8; p++) {
            int dd = wbase + p * 2;
            ull wr0 = *(const ull*)(wrs + dd * WPITCH + 2 * f2);
            ull wr1 = *(const ull*)(wrs + (dd + 1) * WPITCH + 2 * f2);
            ull wc0 = *(const ull*)(wcs + dd * WPITCH + 2 * f2);
            ull wc1 = *(const ull*)(wcs + (dd + 1) * WPITCH + 2 * f2);
#pragma unroll
            for (int r = 0; r < 16; r++) {
                float2 xv = *(const float2*)(xs + r * XP + dd);
                ull x0 = pack2(xv.x);
                ull x1 = pack2(xv.y);
                ffma2(aR[r], x0, wr0);
                ffma2(aR[r], x1, wr1);
                ffma2(aC[r], x0, wc0);
                ffma2(aC[r], x1, wc1);
            }
        }
        __syncthreads();
    }

    // per-warp partials into P: P[(w*2+arr)*16 + r][64]
#pragma unroll
    for (int r = 0; r < 16; r++) {
        *(ull*)(P + ((w * 2 + 0) * 16 + r) * E_ + 2 * f2) = aR[r];
        *(ull*)(P + ((w * 2 + 1) * 16 + r) * E_ + 2 * f2) = aC[r];
    }
    __syncthreads();

    // reduce 8 warp-partials -> raw rows/cols; stash in rS/cS (aliases xs)
    {
        int row = tid >> 4;
        int fq  = tid & 15;
        float4 R4 = make_float4(0.f, 0.f, 0.f, 0.f);
        float4 C4 = make_float4(0.f, 0.f, 0.f, 0.f);
#pragma unroll
        for (int ww = 0; ww < 8; ww++) {
            float4 pr = *(const float4*)(P + ((ww * 2 + 0) * 16 + row) * E_ + fq * 4);
            float4 pc = *(const float4*)(P + ((ww * 2 + 1) * 16 + row) * E_ + fq * 4);
            R4.x += pr.x; R4.y += pr.y; R4.z += pr.z; R4.w += pr.w;
            C4.x += pc.x; C4.y += pc.y; C4.z += pc.z; C4.w += pc.w;
        }
        __syncthreads();   // xs fully consumed; safe to overwrite with rS/cS
        *(float4*)(rS + row * E_ + fq * 4) = R4;
        *(float4*)(cS + row * E_ + fq * 4) = C4;
    }
    __syncthreads();

    // apply W_edges: thread (f = tid&63, rg = tid>>6) handles rows rg*4..rg*4+3
    int f  = tid & 63;
    int rg = tid >> 6;
    float aRf[4] = {0.f, 0.f, 0.f, 0.f};
    float aCf[4] = {0.f, 0.f, 0.f, 0.f};
#pragma unroll 8
    for (int e = 0; e < E_; e++) {
        float wv = wes[e * 65 + f];
#pragma unroll
        for (int rr = 0; rr < 4; rr++) {
            aRf[rr] = fmaf(rS[(rg * 4 + rr) * E_ + e], wv, aRf[rr]);
            aCf[rr] = fmaf(cS[(rg * 4 + rr) * E_ + e], wv, aCf[rr]);
        }
    }

    // stats over the 64 f-lanes of each row (warp pair w, w^1)
    float sR[4], sRR[4], sC[4], sCC[4];
#pragma unroll
    for (int rr = 0; rr < 4; rr++) {
        sR[rr] = aRf[rr]; sRR[rr] = aRf[rr] * aRf[rr];
        sC[rr] = aCf[rr]; sCC[rr] = aCf[rr] * aCf[rr];
#pragma unroll
        for (int o = 16; o; o >>= 1) {
            sR[rr]  += __shfl_xor_sync(0xffffffffu, sR[rr],  o);
            sRR[rr] += __shfl_xor_sync(0xffffffffu, sRR[rr], o);
            sC[rr]  += __shfl_xor_sync(0xffffffffu, sC[rr],  o);
            sCC[rr] += __shfl_xor_sync(0xffffffffu, sCC[rr], o);
        }
    }
    if ((tid & 31) == 0) {
#pragma unroll
        for (int rr = 0; rr < 4; rr++) {
            red[w][rr][0] = sR[rr];  red[w][rr][1] = sRR[rr];
            red[w][rr][2] = sC[rr];  red[w][rr][3] = sCC[rr];
        }
    }
    __syncthreads();

    int wp = w ^ 1;
#pragma unroll
    for (int rr = 0; rr < 4; rr++) {
        float tR  = red[w][rr][0] + red[wp][rr][0];
        float tRR = red[w][rr][1] + red[wp][rr][1];
        float tC  = red[w][rr][2] + red[wp][rr][2];
        float tCC = red[w][rr][3] + red[wp][rr][3];
        float mR = tR * (1.f / 64.f);
        float mC = tC * (1.f / 64.f);
        int grow = row0 + rg * 4 + rr;
        g_Rc[grow * E_ + f] = aRf[rr] - mR;
        g_Cc[grow * E_ + f] = aCf[rr] - mC;
        if (f == 0) {
            g_varR[grow] = tRR * (1.f / 64.f) - mR * mR;
            g_varC[grow] = tCC * (1.f / 64.f) - mC * mC;
        }
    }
}

// ---------------- kernel C: 16x16 tile (known-good R2 version) ---------------
__global__ void __launch_bounds__(256, 4) kC(const float* __restrict__ gamma,
                                             const float* __restrict__ beta,
                                             float* __restrict__ out) {
    __shared__ float rs[16 * PADR];    // raw R'
    __shared__ float cs[16 * PADR];    // raw C' (for dots)
    __shared__ float csg[16 * PADR];   // C' * gamma (for stores)
    __shared__ float vR[16];
    __shared__ float vC[16];
    __shared__ float inv[256];

    int i0 = blockIdx.x * 16;
    int j0 = blockIdx.y * 16;
    int b  = blockIdx.z;
    int tid = threadIdx.x;
    int rowR = b * N_ + i0;
    int rowC = b * N_ + j0;

    for (int idx = tid; idx < 16 * E_; idx += 256) {
        int r = idx >> 6, f = idx & 63;
        float cv = g_Cc[(rowC + r) * E_ + f];
        rs[r * PADR + f]  = g_Rc[(rowR + r) * E_ + f];
        cs[r * PADR + f]  = cv;
        csg[r * PADR + f] = cv * __ldg(gamma + f);
    }
    if (tid < 16)      vR[tid]      = g_varR[rowR + tid];
    else if (tid < 32) vC[tid - 16] = g_varC[rowC + tid - 16];
    __syncthreads();

    // ---- Phase A: one 64-wide dot per thread -> inv std ----
    {
        int ii = tid >> 4, jj = tid & 15;
        const float4* r4 = (const float4*)(rs + ii * PADR);
        const float4* c4 = (const float4*)(cs + jj * PADR);
        float d = 0.f;
#pragma unroll
        for (int k = 0; k < 16; k++) {
            float4 a = r4[k], c = c4[k];
            d = fmaf(a.x, c.x, d);
            d = fmaf(a.y, c.y, d);
            d = fmaf(a.z, c.z, d);
            d = fmaf(a.w, c.w, d);
        }
        float var = vR[ii] + vC[jj] + d * (2.f / 64.f);
        inv[tid] = rsqrtf(var + LN_EPS);
    }
    __syncthreads();

    // ---- Phase B: streaming stores ----
    int f4 = tid & 15;
    int g  = tid >> 4;
    float4 gm = __ldg((const float4*)gamma + f4);
    float4 bt = __ldg((const float4*)beta + f4);
    float4 r  = ((const float4*)(rs + g * PADR))[f4];
    float4 u;
    u.x = r.x * gm.x; u.y = r.y * gm.y; u.z = r.z * gm.z; u.w = r.w * gm.w;

    const float4* ivp = (const float4*)(inv + g * 16);
    float4 iva = ivp[0], ivb = ivp[1], ivc = ivp[2], ivd = ivp[3];
    float ivs[16] = {iva.x, iva.y, iva.z, iva.w, ivb.x, ivb.y, ivb.z, ivb.w,
                     ivc.x, ivc.y, ivc.z, ivc.w, ivd.x, ivd.y, ivd.z, ivd.w};

    float4* op = (float4*)out + ((size_t)(b * N_ + i0 + g) * N_ + j0) * 16 + f4;

#pragma unroll
    for (int jj = 0; jj < 16; jj++) {
        float4 v = ((const float4*)(csg + jj * PADR))[f4];
        float iv = ivs[jj];
        float4 o;
        o.x = fmaf(u.x + v.x, iv, bt.x);
        o.y = fmaf(u.y + v.y, iv, bt.y);
        o.z = fmaf(u.z + v.z, iv, bt.z);
        o.w = fmaf(u.w + v.w, iv, bt.w);
        __stcs(op + (size_t)jj * 16, o);
    }
}

// ---------------- launch -------------------------------------------------------
#define KB_SMEM ((2080 + 8448 + 8448 + 4160) * 4)

extern "C" void kernel_launch(void* const* d_in, const int* in_sizes, int n_in,
                              void* d_out, int out_size) {
    const float* x     = (const float*)d_in[0];  // [2,768,512]
    const float* Wr    = (const float*)d_in[1];  // [64,512]
    const float* Wc    = (const float*)d_in[2];  // [64,512]
    const float* We    = (const float*)d_in[3];  // [64,64]
    const float* gamma = (const float*)d_in[4];  // [64]
    const float* beta  = (const float*)d_in[5];  // [64]
    float* out = (float*)d_out;                  // [2,768,768,64] fp32

    static int smem_set = 0;
    if (!smem_set) {
        cudaFuncSetAttribute(kB, cudaFuncAttributeMaxDynamicSharedMemorySize, KB_SMEM);
        smem_set = 1;
    }

    kB<<<96, 256, KB_SMEM>>>(x, Wr, Wc, We);
    kC<<<dim3(N_ / 16, N_ / 16, B_), 256>>>(gamma, beta, out);
}